// round 16
// baseline (speedup 1.0000x reference)
#include <cuda_runtime.h>
#include <stdint.h>
#include <math.h>

#define B_   32
#define S_   4096
#define H_   768
#define D_   192
#define NS   15
#define NP   16
#define NSEG 4
#define BSEG (B_ / NSEG)        // 8 batches per segment

#define INV_SCALE 0.072168783648703220563f   // 1/sqrt(192)
#define LOG_S     8.3177661667193433f        // log(4096)

// ------------------------------------------------------------------
// device scratch
// ------------------------------------------------------------------
__device__ float g_qk[NP * H_];                 // folded queries (scaled)
__device__ float g_qb[NP];
__device__ float g_Z[B_ * NP];
__device__ float g_L[B_ * NP];
__device__ float g_w[(size_t)B_ * NS * S_];     // exp(logit)
__device__ float g_T[B_ * NS * H_];             // dense weighted-x sums (red.add)
__device__ float g_sep[B_ * NS * D_];           // signal embeds (pre-bias)

// packed f32x2 FMA
__device__ __forceinline__ float2 ffma2(float2 a, float2 b, float2 c) {
    float2 d;
    asm("fma.rn.f32x2 %0, %1, %2, %3;"
        : "=l"(reinterpret_cast<unsigned long long&>(d))
        : "l"(reinterpret_cast<unsigned long long&>(a)),
          "l"(reinterpret_cast<unsigned long long&>(b)),
          "l"(reinterpret_cast<unsigned long long&>(c)));
    return d;
}

__device__ __forceinline__ void cp_async16(unsigned int saddr, const void* gaddr) {
    asm volatile("cp.async.cg.shared.global [%0], [%1], 16;" :: "r"(saddr), "l"(gaddr));
}
__device__ __forceinline__ void cp_async8(unsigned int saddr, const void* gaddr) {
    asm volatile("cp.async.ca.shared.global [%0], [%1], 8;" :: "r"(saddr), "l"(gaddr));
}
#define CP_COMMIT()  asm volatile("cp.async.commit_group;")
#define CP_WAIT(N)   asm volatile("cp.async.wait_group %0;" :: "n"(N))

__device__ __forceinline__ void red_add_v2(float* ptr, float a, float b) {
    asm volatile("red.global.add.v2.f32 [%0], {%1,%2};"
                 :: "l"(ptr), "f"(a), "f"(b) : "memory");
}

// ------------------------------------------------------------------
// zero_T: wide zeroing of g_T (float4 stores). grid 360 x 256.
// ------------------------------------------------------------------
__global__ void zero_T() {
    int idx = blockIdx.x * 256 + threadIdx.x;     // < 92160
    *(float4*)&g_T[idx * 4] = make_float4(0.f, 0.f, 0.f, 0.f);
}

// ------------------------------------------------------------------
// prep: g_qk = (Wk @ q_n)/sqrt(d), g_qb; zero Z/L
// ------------------------------------------------------------------
__global__ void prep_kernel(const float* __restrict__ SQ,
                            const float* __restrict__ Wk,
                            const float* __restrict__ bk) {
    int idx = blockIdx.x * 256 + threadIdx.x;   // 0..12287
    int h = idx >> 4, n = idx & 15;
    float v = 0.f;
    if (n < NS) {
        float s = 0.f;
        const float* q = SQ + n * D_;
        const float* w = Wk + h * D_;
#pragma unroll 8
        for (int d = 0; d < D_; d++) s += q[d] * w[d];
        v = s * INV_SCALE;
    }
    g_qk[n * H_ + h] = v;
    if (idx < NP) {
        float s = 0.f;
        if (idx < NS) {
            const float* q = SQ + idx * D_;
            for (int d = 0; d < D_; d++) s += q[d] * bk[d];
        }
        g_qb[idx] = s * INV_SCALE;
    }
    if (idx < B_ * NP) { g_Z[idx] = 0.f; g_L[idx] = 0.f; }
}

// ------------------------------------------------------------------
// pass A: logits + exp + Z/L. grid (32 schunks, BSEG), 128 thr.
// Exact R11 configuration, batch offset b0.
// ------------------------------------------------------------------
#define PA_XSTRIDE 36
#define PA_QSTRIDE 34
#define PA_XS0 0
#define PA_XS1 (128 * PA_XSTRIDE)
#define PA_QK0 (2 * 128 * PA_XSTRIDE)
#define PA_QK1 (PA_QK0 + 16 * PA_QSTRIDE)
#define PA_SMEMF (PA_QK1 + 16 * PA_QSTRIDE)
#define NCH 24

__global__ __launch_bounds__(128) void pass_a(const float* __restrict__ X, int b0) {
    extern __shared__ float sm[];
    __shared__ float zs[16], ls[16];

    const int b   = b0 + blockIdx.y;
    const int s0  = blockIdx.x << 7;
    const int tid = threadIdx.x;
    const int sgrp = tid & 3;
    const int tgrp = tid >> 2;

    const float* xbase = X + (size_t)(b * S_ + s0) * H_;
    const unsigned int smb = (unsigned int)__cvta_generic_to_shared(sm);

    if (tid < 16) { zs[tid] = 0.f; ls[tid] = 0.f; }

    float2 acc[4][4];
#pragma unroll
    for (int i = 0; i < 4; i++)
#pragma unroll
        for (int j = 0; j < 4; j++) acc[i][j] = make_float2(0.f, 0.f);

    {
        const int hc = 0;
        unsigned int xd = smb + PA_XS0 * 4;
        unsigned int qd = smb + PA_QK0 * 4;
#pragma unroll
        for (int k = 0; k < 8; k++) {
            int idx = tid + (k << 7);
            int tok = idx >> 3, c4 = idx & 7;
            cp_async16(xd + (tok * PA_XSTRIDE + c4 * 4) * 4,
                       xbase + (size_t)tok * H_ + hc + c4 * 4);
        }
#pragma unroll
        for (int k = 0; k < 2; k++) {
            int idx = tid + (k << 7);
            int n = idx >> 4, c2 = idx & 15;
            cp_async8(qd + (n * PA_QSTRIDE + c2 * 2) * 4,
                      g_qk + n * H_ + hc + c2 * 2);
        }
        CP_COMMIT();
    }

    for (int c = 0; c < NCH; c++) {
        if (c + 1 < NCH) {
            const int hc = (c + 1) << 5;
            const int nb = (c + 1) & 1;
            unsigned int xd = smb + (nb ? PA_XS1 : PA_XS0) * 4;
            unsigned int qd = smb + (nb ? PA_QK1 : PA_QK0) * 4;
#pragma unroll
            for (int k = 0; k < 8; k++) {
                int idx = tid + (k << 7);
                int tok = idx >> 3, c4 = idx & 7;
                cp_async16(xd + (tok * PA_XSTRIDE + c4 * 4) * 4,
                           xbase + (size_t)tok * H_ + hc + c4 * 4);
            }
#pragma unroll
            for (int k = 0; k < 2; k++) {
                int idx = tid + (k << 7);
                int n = idx >> 4, c2 = idx & 15;
                cp_async8(qd + (n * PA_QSTRIDE + c2 * 2) * 4,
                          g_qk + n * H_ + hc + c2 * 2);
            }
            CP_COMMIT();
            CP_WAIT(1);
        } else {
            CP_WAIT(0);
        }
        __syncthreads();

        const float* xs  = sm + ((c & 1) ? PA_XS1 : PA_XS0);
        const float* qks = sm + ((c & 1) ? PA_QK1 : PA_QK0);

#pragma unroll
        for (int h2 = 0; h2 < 16; h2++) {
            float2 qv[4];
#pragma unroll
            for (int j = 0; j < 4; j++)
                qv[j] = *(const float2*)&qks[(sgrp * 4 + j) * PA_QSTRIDE + h2 * 2];
#pragma unroll
            for (int i = 0; i < 4; i++) {
                float2 xv = *(const float2*)&xs[(tgrp + (i << 5)) * PA_XSTRIDE + h2 * 2];
#pragma unroll
                for (int j = 0; j < 4; j++) acc[i][j] = ffma2(xv, qv[j], acc[i][j]);
            }
        }
        __syncthreads();
    }

    float qb[4];
#pragma unroll
    for (int j = 0; j < 4; j++) qb[j] = g_qb[sgrp * 4 + j];

    float zp[4] = {0.f, 0.f, 0.f, 0.f}, lp[4] = {0.f, 0.f, 0.f, 0.f};
#pragma unroll
    for (int i = 0; i < 4; i++) {
        int s = s0 + tgrp + (i << 5);
#pragma unroll
        for (int j = 0; j < 4; j++) {
            int n = sgrp * 4 + j;
            float l = acc[i][j].x + acc[i][j].y + qb[j];
            float w = __expf(l);
            zp[j] += w;
            lp[j] += w * l;
            if (n < NS) g_w[((size_t)(b * NS + n)) * S_ + s] = w;
        }
    }
#pragma unroll
    for (int j = 0; j < 4; j++) {
        atomicAdd(&zs[sgrp * 4 + j], zp[j]);
        atomicAdd(&ls[sgrp * 4 + j], lp[j]);
    }
    __syncthreads();
    if (tid < 16) {
        atomicAdd(&g_Z[b * NP + tid], zs[tid]);
        atomicAdd(&g_L[b * NP + tid], ls[tid]);
    }
}

// ------------------------------------------------------------------
// pass B: g_T[b][n][h] += sum_s w*x via red.global.add.v2.
// grid (8 sc, 2 hc, BSEG), 192 thr. Batch offset b0. R12 config.
// ------------------------------------------------------------------
__global__ __launch_bounds__(192) void pass_b(const float* __restrict__ X, int b0) {
    __shared__ float ws[2][NS * 128];

    const int sc  = blockIdx.x;
    const int hc  = blockIdx.y;
    const int b   = b0 + blockIdx.z;
    const int tid = threadIdx.x;
    const int sbeg = sc * 512;
    const int hoff = hc * 384 + tid * 2;

    const unsigned int wsb = (unsigned int)__cvta_generic_to_shared(&ws[0][0]);
    const size_t wrow = (size_t)b * NS * S_;

    float2 acc[NS];
#pragma unroll
    for (int n = 0; n < NS; n++) acc[n] = make_float2(0.f, 0.f);

#pragma unroll
    for (int k = 0; k < 3; k++) {
        int idx = tid + k * 192;
        if (idx < NS * 32) {
            int n = idx >> 5, c4 = idx & 31;
            cp_async16(wsb + (n * 128 + c4 * 4) * 4,
                       g_w + wrow + (size_t)n * S_ + sbeg + c4 * 4);
        }
    }
    CP_COMMIT();

    const float* xp = X + (size_t)(b * S_ + sbeg) * H_ + hoff;

    for (int t = 0; t < 4; t++) {
        if (t + 1 < 4) {
            unsigned int dst = wsb + ((t + 1) & 1) * (NS * 128 * 4);
#pragma unroll
            for (int k = 0; k < 3; k++) {
                int idx = tid + k * 192;
                if (idx < NS * 32) {
                    int n = idx >> 5, c4 = idx & 31;
                    cp_async16(dst + (n * 128 + c4 * 4) * 4,
                               g_w + wrow + (size_t)n * S_ + sbeg + (t + 1) * 128 + c4 * 4);
                }
            }
            CP_COMMIT();
            CP_WAIT(1);
        } else {
            CP_WAIT(0);
        }
        __syncthreads();

        const float* wt = ws[t & 1];
#pragma unroll 2
        for (int sg = 0; sg < 128; sg += 4) {
            float2 xv[4];
#pragma unroll
            for (int u = 0; u < 4; u++)
                xv[u] = *(const float2*)(xp + (size_t)(sg + u) * H_);
#pragma unroll
            for (int n = 0; n < NS; n++) {
                float4 w4 = *(const float4*)&wt[n * 128 + sg];
                acc[n] = ffma2(make_float2(w4.x, w4.x), xv[0], acc[n]);
                acc[n] = ffma2(make_float2(w4.y, w4.y), xv[1], acc[n]);
                acc[n] = ffma2(make_float2(w4.z, w4.z), xv[2], acc[n]);
                acc[n] = ffma2(make_float2(w4.w, w4.w), xv[3], acc[n]);
            }
        }
        xp += (size_t)128 * H_;
        __syncthreads();
    }

#pragma unroll
    for (int n = 0; n < NS; n++)
        red_add_v2(&g_T[(b * NS + n) * H_ + hoff], acc[n].x, acc[n].y);
}

// ------------------------------------------------------------------
// wv_kernel: se[b][n][d] = (g_T[b][n][:]/Z) @ Wv.
// grid (NS, 8), 384 thr = 4 h-quarters x 96 d-pairs; 4 batches/block.
// ------------------------------------------------------------------
__global__ __launch_bounds__(384) void wv_kernel(const float* __restrict__ Wv) {
    __shared__ float4 ts4[H_];              // [h] -> t for 4 batches
    __shared__ float invz[4];
    __shared__ float2 part[4][96][4];       // [hq][dp][b]
    const int n  = blockIdx.x;
    const int bg = blockIdx.y;
    const int tid = threadIdx.x;

    if (tid < 4) invz[tid] = 1.0f / g_Z[(bg * 4 + tid) * NP + n];
    __syncthreads();

#pragma unroll
    for (int k = 0; k < 8; k++) {
        int i = tid + k * 384;
        int bb = i / H_, hh = i - bb * H_;
        ((float*)&ts4[hh])[bb] =
            g_T[((bg * 4 + bb) * NS + n) * H_ + hh] * invz[bb];
    }
    __syncthreads();

    const int hq = tid / 96;
    const int dp = tid - hq * 96;

    float2 a0 = make_float2(0.f,0.f), a1 = a0, a2 = a0, a3 = a0;
#pragma unroll 4
    for (int hh = 0; hh < 192; hh++) {
        int h = hq * 192 + hh;
        float2 wv2 = *(const float2*)(Wv + (size_t)h * D_ + 2 * dp);
        float4 tv = ts4[h];
        a0 = ffma2(wv2, make_float2(tv.x, tv.x), a0);
        a1 = ffma2(wv2, make_float2(tv.y, tv.y), a1);
        a2 = ffma2(wv2, make_float2(tv.z, tv.z), a2);
        a3 = ffma2(wv2, make_float2(tv.w, tv.w), a3);
    }
    part[hq][dp][0] = a0; part[hq][dp][1] = a1;
    part[hq][dp][2] = a2; part[hq][dp][3] = a3;
    __syncthreads();

    {
        int dp2 = tid >> 2, b = tid & 3;
        float2 s0 = part[0][dp2][b], s1 = part[1][dp2][b];
        float2 s2 = part[2][dp2][b], s3 = part[3][dp2][b];
        float2 s = make_float2(s0.x + s1.x + s2.x + s3.x,
                               s0.y + s1.y + s2.y + s3.y);
        *(float2*)&g_sep[((bg * 4 + b) * NS + n) * D_ + 2 * dp2] = s;
    }
}

// ------------------------------------------------------------------
// R3: MLP head + strength. One block per batch (32 blocks, 256 thr).
// ------------------------------------------------------------------
#define R3_W1  0
#define R3_EFF 24576
#define R3_GH  (24576 + 15 * 384)
#define R3_SMEMF (R3_GH + 960)

__global__ __launch_bounds__(256) void r3_kernel(
    const float* __restrict__ bv, const float* __restrict__ NE,
    const float* __restrict__ W1, const float* __restrict__ b1,
    const float* __restrict__ W2, const float* __restrict__ b2,
    float* __restrict__ out) {
    extern __shared__ float sm[];
    float* W1s = sm + R3_W1;
    float* eff = sm + R3_EFF;   // [15][384]
    float* gh  = sm + R3_GH;    // [960]
    const int b = blockIdx.x, tid = threadIdx.x;

    {
        float4* d = (float4*)W1s;
        const float4* s = (const float4*)W1;
#pragma unroll
        for (int k = 0; k < 24; k++) d[tid + 256 * k] = s[tid + 256 * k];
    }
    for (int i = tid; i < NS * 384; i += 256) {
        int n = i / 384, ii = i - n * 384;
        float v;
        if (ii < D_) v = bv[ii] + g_sep[(b * NS + n) * D_ + ii];
        else         v = NE[(size_t)n * H_ + (ii - D_)];
        eff[i] = v;
    }
    __syncthreads();

#pragma unroll
    for (int k = 0; k < 4; k++) {
        int u = tid + 256 * k;
        if (u < NS * 64) {
            int n = u >> 6, j = u & 63;
            const float* e = eff + n * 384;
            float h0 = b1[j], h1 = 0.f;
#pragma unroll 4
            for (int i = 0; i < 384; i += 2) {
                h0 = fmaf(e[i],     W1s[i * 64 + j],       h0);
                h1 = fmaf(e[i + 1], W1s[(i + 1) * 64 + j], h1);
            }
            float h = h0 + h1;
            gh[u] = 0.5f * h * (1.0f + erff(h * 0.70710678118654752f));
        }
    }
    if (tid < NS) {
        float Z = g_Z[b * NP + tid], L = g_L[b * NP + tid];
        float ent = logf(Z) - L / Z;
        out[b * (2 * NS) + NS + tid] = 1.0f - ent * (1.0f / LOG_S);
    }
    __syncthreads();

    int wid = tid >> 5, lid = tid & 31;
#pragma unroll
    for (int r = 0; r < 2; r++) {
        int n = wid * 2 + r;
        if (n < NS) {
            float v = gh[n * 64 + lid] * W2[lid] + gh[n * 64 + lid + 32] * W2[lid + 32];
#pragma unroll
            for (int o = 16; o; o >>= 1) v += __shfl_xor_sync(0xffffffffu, v, o);
            if (lid == 0) out[b * (2 * NS) + n] = v + b2[0];
        }
    }
}

// ------------------------------------------------------------------
extern "C" void kernel_launch(void* const* d_in, const int* in_sizes, int n_in,
                              void* d_out, int out_size) {
    const float* X   = (const float*)d_in[0];
    const float* Wk  = (const float*)d_in[1];
    const float* bk  = (const float*)d_in[2];
    const float* Wv  = (const float*)d_in[3];
    const float* bv  = (const float*)d_in[4];
    const float* SQ  = (const float*)d_in[5];
    const float* NE  = (const float*)d_in[6];
    const float* W1  = (const float*)d_in[7];
    const float* b1  = (const float*)d_in[8];
    const float* W2  = (const float*)d_in[9];
    const float* b2  = (const float*)d_in[10];
    float* out = (float*)d_out;                 // [32,30]

    // one-time resource init (correctness call runs uncaptured first)
    static cudaStream_t s2 = 0;
    static cudaEvent_t evF, evJ, evA[NSEG];
    if (!s2) {
        cudaStreamCreateWithFlags(&s2, cudaStreamNonBlocking);
        cudaEventCreateWithFlags(&evF, cudaEventDisableTiming);
        cudaEventCreateWithFlags(&evJ, cudaEventDisableTiming);
        for (int g = 0; g < NSEG; g++)
            cudaEventCreateWithFlags(&evA[g], cudaEventDisableTiming);
        cudaFuncSetAttribute(pass_a, cudaFuncAttributeMaxDynamicSharedMemorySize,
                             PA_SMEMF * 4);
        cudaFuncSetAttribute(r3_kernel, cudaFuncAttributeMaxDynamicSharedMemorySize,
                             R3_SMEMF * 4);
    }

    // main stream: prep; fork s2
    prep_kernel<<<48, 256>>>(SQ, Wk, bk);
    cudaEventRecord(evF, 0);
    cudaStreamWaitEvent(s2, evF, 0);
    zero_T<<<360, 256, 0, s2>>>();

    // pipelined segments: pass_a(g) on stream 0, pass_b(g) on s2
    for (int g = 0; g < NSEG; g++) {
        pass_a<<<dim3(32, BSEG), 128, PA_SMEMF * 4>>>(X, g * BSEG);
        cudaEventRecord(evA[g], 0);
        cudaStreamWaitEvent(s2, evA[g], 0);
        pass_b<<<dim3(8, 2, BSEG), 192, 0, s2>>>(X, g * BSEG);
    }

    // join s2 back into stream 0
    cudaEventRecord(evJ, s2);
    cudaStreamWaitEvent(0, evJ, 0);

    wv_kernel<<<dim3(NS, 8), 384>>>(Wv);
    r3_kernel<<<B_, 256, R3_SMEMF * 4>>>(bv, NE, W1, b1, W2, b2, out);
}

// round 17
// speedup vs baseline: 2.2813x; 2.2813x over previous
#include <cuda_runtime.h>
#include <stdint.h>
#include <math.h>

#define B_   32
#define S_   4096
#define H_   768
#define D_   192
#define NS   15
#define NP   16

#define INV_SCALE 0.072168783648703220563f   // 1/sqrt(192)
#define LOG_S     8.3177661667193433f        // log(4096)

// ------------------------------------------------------------------
// device scratch
// ------------------------------------------------------------------
__device__ float g_qk[NP * H_];                 // folded queries (scaled)
__device__ float g_qb[NP];
__device__ float g_Z[B_ * NP];
__device__ float g_L[B_ * NP];
__device__ float g_w[(size_t)B_ * NS * S_];     // exp(logit)
__device__ float g_T[B_ * NS * H_];             // dense weighted-x sums (red.add)
__device__ float g_sep[B_ * NS * D_];           // signal embeds (pre-bias)

// packed f32x2 FMA
__device__ __forceinline__ float2 ffma2(float2 a, float2 b, float2 c) {
    float2 d;
    asm("fma.rn.f32x2 %0, %1, %2, %3;"
        : "=l"(reinterpret_cast<unsigned long long&>(d))
        : "l"(reinterpret_cast<unsigned long long&>(a)),
          "l"(reinterpret_cast<unsigned long long&>(b)),
          "l"(reinterpret_cast<unsigned long long&>(c)));
    return d;
}

__device__ __forceinline__ void cp_async16(unsigned int saddr, const void* gaddr) {
    asm volatile("cp.async.cg.shared.global [%0], [%1], 16;" :: "r"(saddr), "l"(gaddr));
}
__device__ __forceinline__ void cp_async8(unsigned int saddr, const void* gaddr) {
    asm volatile("cp.async.ca.shared.global [%0], [%1], 8;" :: "r"(saddr), "l"(gaddr));
}
#define CP_COMMIT()  asm volatile("cp.async.commit_group;")
#define CP_WAIT(N)   asm volatile("cp.async.wait_group %0;" :: "n"(N))

__device__ __forceinline__ void red_add_v2(float* ptr, float a, float b) {
    asm volatile("red.global.add.v2.f32 [%0], {%1,%2};"
                 :: "l"(ptr), "f"(a), "f"(b) : "memory");
}
__device__ __forceinline__ void red_add_f32(float* ptr, float a) {
    asm volatile("red.global.add.f32 [%0], %1;" :: "l"(ptr), "f"(a) : "memory");
}

// ------------------------------------------------------------------
// prep: g_qk = (Wk @ q_n)/sqrt(d), g_qb; zero Z/L and g_T
// ------------------------------------------------------------------
__global__ void prep_kernel(const float* __restrict__ SQ,
                            const float* __restrict__ Wk,
                            const float* __restrict__ bk) {
    int idx = blockIdx.x * 256 + threadIdx.x;   // 0..12287
    int h = idx >> 4, n = idx & 15;
    float v = 0.f;
    if (n < NS) {
        float s = 0.f;
        const float* q = SQ + n * D_;
        const float* w = Wk + h * D_;
#pragma unroll 8
        for (int d = 0; d < D_; d++) s += q[d] * w[d];
        v = s * INV_SCALE;
    }
    g_qk[n * H_ + h] = v;
    if (idx < NP) {
        float s = 0.f;
        if (idx < NS) {
            const float* q = SQ + idx * D_;
            for (int d = 0; d < D_; d++) s += q[d] * bk[d];
        }
        g_qb[idx] = s * INV_SCALE;
    }
    if (idx < B_ * NP) { g_Z[idx] = 0.f; g_L[idx] = 0.f; }
#pragma unroll
    for (int k = 0; k < 30; k++)            // 30*12288 = B*NS*H
        g_T[idx + k * 12288] = 0.f;
}

// ------------------------------------------------------------------
// pass A: logits + exp + Z/L. grid (32 schunks, 32 b), 128 thr.
// 128 tokens/block, h in 32-chunks, cp.async double-buffered.
// Thread tile: 4 tok x 4 sig. smem 41216 B.
// ------------------------------------------------------------------
#define PA_XSTRIDE 36
#define PA_QSTRIDE 34
#define PA_XS0 0
#define PA_XS1 (128 * PA_XSTRIDE)
#define PA_QK0 (2 * 128 * PA_XSTRIDE)
#define PA_QK1 (PA_QK0 + 16 * PA_QSTRIDE)
#define PA_SMEMF (PA_QK1 + 16 * PA_QSTRIDE)
#define NCH 24

__global__ __launch_bounds__(128) void pass_a(const float* __restrict__ X) {
    extern __shared__ float sm[];
    __shared__ float zs[16], ls[16];

    const int b   = blockIdx.y;
    const int s0  = blockIdx.x << 7;
    const int tid = threadIdx.x;
    const int sgrp = tid & 3;
    const int tgrp = tid >> 2;

    const float* xbase = X + (size_t)(b * S_ + s0) * H_;
    const unsigned int smb = (unsigned int)__cvta_generic_to_shared(sm);

    if (tid < 16) { zs[tid] = 0.f; ls[tid] = 0.f; }

    float2 acc[4][4];
#pragma unroll
    for (int i = 0; i < 4; i++)
#pragma unroll
        for (int j = 0; j < 4; j++) acc[i][j] = make_float2(0.f, 0.f);

    {
        const int hc = 0;
        unsigned int xd = smb + PA_XS0 * 4;
        unsigned int qd = smb + PA_QK0 * 4;
#pragma unroll
        for (int k = 0; k < 8; k++) {
            int idx = tid + (k << 7);
            int tok = idx >> 3, c4 = idx & 7;
            cp_async16(xd + (tok * PA_XSTRIDE + c4 * 4) * 4,
                       xbase + (size_t)tok * H_ + hc + c4 * 4);
        }
#pragma unroll
        for (int k = 0; k < 2; k++) {
            int idx = tid + (k << 7);
            int n = idx >> 4, c2 = idx & 15;
            cp_async8(qd + (n * PA_QSTRIDE + c2 * 2) * 4,
                      g_qk + n * H_ + hc + c2 * 2);
        }
        CP_COMMIT();
    }

    for (int c = 0; c < NCH; c++) {
        if (c + 1 < NCH) {
            const int hc = (c + 1) << 5;
            const int nb = (c + 1) & 1;
            unsigned int xd = smb + (nb ? PA_XS1 : PA_XS0) * 4;
            unsigned int qd = smb + (nb ? PA_QK1 : PA_QK0) * 4;
#pragma unroll
            for (int k = 0; k < 8; k++) {
                int idx = tid + (k << 7);
                int tok = idx >> 3, c4 = idx & 7;
                cp_async16(xd + (tok * PA_XSTRIDE + c4 * 4) * 4,
                           xbase + (size_t)tok * H_ + hc + c4 * 4);
            }
#pragma unroll
            for (int k = 0; k < 2; k++) {
                int idx = tid + (k << 7);
                int n = idx >> 4, c2 = idx & 15;
                cp_async8(qd + (n * PA_QSTRIDE + c2 * 2) * 4,
                          g_qk + n * H_ + hc + c2 * 2);
            }
            CP_COMMIT();
            CP_WAIT(1);
        } else {
            CP_WAIT(0);
        }
        __syncthreads();

        const float* xs  = sm + ((c & 1) ? PA_XS1 : PA_XS0);
        const float* qks = sm + ((c & 1) ? PA_QK1 : PA_QK0);

#pragma unroll
        for (int h2 = 0; h2 < 16; h2++) {
            float2 qv[4];
#pragma unroll
            for (int j = 0; j < 4; j++)
                qv[j] = *(const float2*)&qks[(sgrp * 4 + j) * PA_QSTRIDE + h2 * 2];
#pragma unroll
            for (int i = 0; i < 4; i++) {
                float2 xv = *(const float2*)&xs[(tgrp + (i << 5)) * PA_XSTRIDE + h2 * 2];
#pragma unroll
                for (int j = 0; j < 4; j++) acc[i][j] = ffma2(xv, qv[j], acc[i][j]);
            }
        }
        __syncthreads();
    }

    float qb[4];
#pragma unroll
    for (int j = 0; j < 4; j++) qb[j] = g_qb[sgrp * 4 + j];

    float zp[4] = {0.f, 0.f, 0.f, 0.f}, lp[4] = {0.f, 0.f, 0.f, 0.f};
#pragma unroll
    for (int i = 0; i < 4; i++) {
        int s = s0 + tgrp + (i << 5);
#pragma unroll
        for (int j = 0; j < 4; j++) {
            int n = sgrp * 4 + j;
            float l = acc[i][j].x + acc[i][j].y + qb[j];
            float w = __expf(l);
            zp[j] += w;
            lp[j] += w * l;
            if (n < NS) g_w[((size_t)(b * NS + n)) * S_ + s] = w;
        }
    }
#pragma unroll
    for (int j = 0; j < 4; j++) {
        atomicAdd(&zs[sgrp * 4 + j], zp[j]);
        atomicAdd(&ls[sgrp * 4 + j], lp[j]);
    }
    __syncthreads();
    if (tid < 16) {
        atomicAdd(&g_Z[b * NP + tid], zs[tid]);
        atomicAdd(&g_L[b * NP + tid], ls[tid]);
    }
}

// ------------------------------------------------------------------
// pass B: g_T[b][n][h] += sum_s w*x via red.global.add.v2.
// grid (8 sc, 2 hc, 32 b), 192 thr. Thread owns h-float2.
// ------------------------------------------------------------------
__global__ __launch_bounds__(192) void pass_b(const float* __restrict__ X) {
    __shared__ float ws[2][NS * 128];

    const int sc  = blockIdx.x;
    const int hc  = blockIdx.y;
    const int b   = blockIdx.z;
    const int tid = threadIdx.x;
    const int sbeg = sc * 512;
    const int hoff = hc * 384 + tid * 2;

    const unsigned int wsb = (unsigned int)__cvta_generic_to_shared(&ws[0][0]);
    const size_t wrow = (size_t)b * NS * S_;

    float2 acc[NS];
#pragma unroll
    for (int n = 0; n < NS; n++) acc[n] = make_float2(0.f, 0.f);

#pragma unroll
    for (int k = 0; k < 3; k++) {
        int idx = tid + k * 192;
        if (idx < NS * 32) {
            int n = idx >> 5, c4 = idx & 31;
            cp_async16(wsb + (n * 128 + c4 * 4) * 4,
                       g_w + wrow + (size_t)n * S_ + sbeg + c4 * 4);
        }
    }
    CP_COMMIT();

    const float* xp = X + (size_t)(b * S_ + sbeg) * H_ + hoff;

    for (int t = 0; t < 4; t++) {
        if (t + 1 < 4) {
            unsigned int dst = wsb + ((t + 1) & 1) * (NS * 128 * 4);
#pragma unroll
            for (int k = 0; k < 3; k++) {
                int idx = tid + k * 192;
                if (idx < NS * 32) {
                    int n = idx >> 5, c4 = idx & 31;
                    cp_async16(dst + (n * 128 + c4 * 4) * 4,
                               g_w + wrow + (size_t)n * S_ + sbeg + (t + 1) * 128 + c4 * 4);
                }
            }
            CP_COMMIT();
            CP_WAIT(1);
        } else {
            CP_WAIT(0);
        }
        __syncthreads();

        const float* wt = ws[t & 1];
#pragma unroll 2
        for (int sg = 0; sg < 128; sg += 4) {
            float2 xv[4];
#pragma unroll
            for (int u = 0; u < 4; u++)
                xv[u] = *(const float2*)(xp + (size_t)(sg + u) * H_);
#pragma unroll
            for (int n = 0; n < NS; n++) {
                float4 w4 = *(const float4*)&wt[n * 128 + sg];
                acc[n] = ffma2(make_float2(w4.x, w4.x), xv[0], acc[n]);
                acc[n] = ffma2(make_float2(w4.y, w4.y), xv[1], acc[n]);
                acc[n] = ffma2(make_float2(w4.z, w4.z), xv[2], acc[n]);
                acc[n] = ffma2(make_float2(w4.w, w4.w), xv[3], acc[n]);
            }
        }
        xp += (size_t)128 * H_;
        __syncthreads();
    }

#pragma unroll
    for (int n = 0; n < NS; n++)
        red_add_v2(&g_T[(b * NS + n) * H_ + hoff], acc[n].x, acc[n].y);
}

// ------------------------------------------------------------------
// wv_kernel: se[b][n][d] = (g_T[b][n][:]/Z) @ Wv.
// grid (NS, 8), 384 thr = 4 h-quarters x 96 d-pairs; 4 batches/block.
// ------------------------------------------------------------------
__global__ __launch_bounds__(384) void wv_kernel(const float* __restrict__ Wv) {
    __shared__ float4 ts4[H_];              // [h] -> t for 4 batches
    __shared__ float invz[4];
    __shared__ float2 part[4][96][4];       // [hq][dp][b]
    const int n  = blockIdx.x;
    const int bg = blockIdx.y;
    const int tid = threadIdx.x;

    if (tid < 4) invz[tid] = 1.0f / g_Z[(bg * 4 + tid) * NP + n];
    __syncthreads();

#pragma unroll
    for (int k = 0; k < 8; k++) {
        int i = tid + k * 384;
        int bb = i / H_, hh = i - bb * H_;
        ((float*)&ts4[hh])[bb] =
            g_T[((bg * 4 + bb) * NS + n) * H_ + hh] * invz[bb];
    }
    __syncthreads();

    const int hq = tid / 96;
    const int dp = tid - hq * 96;

    float2 a0 = make_float2(0.f,0.f), a1 = a0, a2 = a0, a3 = a0;
#pragma unroll 4
    for (int hh = 0; hh < 192; hh++) {
        int h = hq * 192 + hh;
        float2 wv2 = *(const float2*)(Wv + (size_t)h * D_ + 2 * dp);
        float4 tv = ts4[h];
        a0 = ffma2(wv2, make_float2(tv.x, tv.x), a0);
        a1 = ffma2(wv2, make_float2(tv.y, tv.y), a1);
        a2 = ffma2(wv2, make_float2(tv.z, tv.z), a2);
        a3 = ffma2(wv2, make_float2(tv.w, tv.w), a3);
    }
    part[hq][dp][0] = a0; part[hq][dp][1] = a1;
    part[hq][dp][2] = a2; part[hq][dp][3] = a3;
    __syncthreads();

    {
        int dp2 = tid >> 2, b = tid & 3;
        float2 s0 = part[0][dp2][b], s1 = part[1][dp2][b];
        float2 s2 = part[2][dp2][b], s3 = part[3][dp2][b];
        float2 s = make_float2(s0.x + s1.x + s2.x + s3.x,
                               s0.y + s1.y + s2.y + s3.y);
        *(float2*)&g_sep[((bg * 4 + b) * NS + n) * D_ + 2 * dp2] = s;
    }
}

// ------------------------------------------------------------------
// R3: MLP head + strength. One block per batch (32 blocks, 256 thr).
// ------------------------------------------------------------------
#define R3_W1  0
#define R3_EFF 24576
#define R3_GH  (24576 + 15 * 384)
#define R3_SMEMF (R3_GH + 960)

__global__ __launch_bounds__(256) void r3_kernel(
    const float* __restrict__ bv, const float* __restrict__ NE,
    const float* __restrict__ W1, const float* __restrict__ b1,
    const float* __restrict__ W2, const float* __restrict__ b2,
    float* __restrict__ out) {
    extern __shared__ float sm[];
    float* W1s = sm + R3_W1;
    float* eff = sm + R3_EFF;   // [15][384]
    float* gh  = sm + R3_GH;    // [960]
    const int b = blockIdx.x, tid = threadIdx.x;

    {
        float4* d = (float4*)W1s;
        const float4* s = (const float4*)W1;
#pragma unroll
        for (int k = 0; k < 24; k++) d[tid + 256 * k] = s[tid + 256 * k];
    }
    for (int i = tid; i < NS * 384; i += 256) {
        int n = i / 384, ii = i - n * 384;
        float v;
        if (ii < D_) v = bv[ii] + g_sep[(b * NS + n) * D_ + ii];
        else         v = NE[(size_t)n * H_ + (ii - D_)];
        eff[i] = v;
    }
    __syncthreads();

#pragma unroll
    for (int k = 0; k < 4; k++) {
        int u = tid + 256 * k;
        if (u < NS * 64) {
            int n = u >> 6, j = u & 63;
            const float* e = eff + n * 384;
            float h0 = b1[j], h1 = 0.f;
#pragma unroll 4
            for (int i = 0; i < 384; i += 2) {
                h0 = fmaf(e[i],     W1s[i * 64 + j],       h0);
                h1 = fmaf(e[i + 1], W1s[(i + 1) * 64 + j], h1);
            }
            float h = h0 + h1;
            gh[u] = 0.5f * h * (1.0f + erff(h * 0.70710678118654752f));
        }
    }
    if (tid < NS) {
        float Z = g_Z[b * NP + tid], L = g_L[b * NP + tid];
        float ent = logf(Z) - L / Z;
        out[b * (2 * NS) + NS + tid] = 1.0f - ent * (1.0f / LOG_S);
    }
    __syncthreads();

    int wid = tid >> 5, lid = tid & 31;
#pragma unroll
    for (int r = 0; r < 2; r++) {
        int n = wid * 2 + r;
        if (n < NS) {
            float v = gh[n * 64 + lid] * W2[lid] + gh[n * 64 + lid + 32] * W2[lid + 32];
#pragma unroll
            for (int o = 16; o; o >>= 1) v += __shfl_xor_sync(0xffffffffu, v, o);
            if (lid == 0) out[b * (2 * NS) + n] = v + b2[0];
        }
    }
}

// ------------------------------------------------------------------
extern "C" void kernel_launch(void* const* d_in, const int* in_sizes, int n_in,
                              void* d_out, int out_size) {
    const float* X   = (const float*)d_in[0];
    const float* Wk  = (const float*)d_in[1];
    const float* bk  = (const float*)d_in[2];
    const float* Wv  = (const float*)d_in[3];
    const float* bv  = (const float*)d_in[4];
    const float* SQ  = (const float*)d_in[5];
    const float* NE  = (const float*)d_in[6];
    const float* W1  = (const float*)d_in[7];
    const float* b1  = (const float*)d_in[8];
    const float* W2  = (const float*)d_in[9];
    const float* b2  = (const float*)d_in[10];
    float* out = (float*)d_out;                 // [32,30]

    cudaFuncSetAttribute(pass_a, cudaFuncAttributeMaxDynamicSharedMemorySize,
                         PA_SMEMF * 4);
    cudaFuncSetAttribute(r3_kernel, cudaFuncAttributeMaxDynamicSharedMemorySize,
                         R3_SMEMF * 4);

    prep_kernel<<<48, 256>>>(SQ, Wk, bk);
    pass_a<<<dim3(32, B_), 128, PA_SMEMF * 4>>>(X);
    pass_b<<<dim3(8, 2, B_), 192>>>(X);
    wv_kernel<<<dim3(NS, 8), 384>>>(Wv);
    r3_kernel<<<B_, 256, R3_SMEMF * 4>>>(bv, NE, W1, b1, W2, b2, out);
}